// round 1
// baseline (speedup 1.0000x reference)
#include <cuda_runtime.h>

// Problem constants (match reference setup_inputs)
#define N_NODES 50000
#define D_FEAT  128
#define K_TOT   256      // 2 * D_FEAT
#define N_EDGES 625000

// Scratch for aggregated neighborhood features [N, 128] (allocation-free rule:
// use a __device__ global).
__device__ float g_agg[(size_t)N_NODES * D_FEAT];

// ---------------------------------------------------------------------------
// Kernel 1: warp-per-node segmented reduction.
// dst is sorted ascending, so node i's edges are the contiguous range
// [lower_bound(dst,i), lower_bound(dst,i+1)). Each warp owns one node; each
// lane owns 4 features (float4). No atomics.
// ---------------------------------------------------------------------------
__device__ __forceinline__ int lower_bound_i(const int* __restrict__ a, int n, int v) {
    int lo = 0, hi = n;
    while (lo < hi) {
        int mid = (lo + hi) >> 1;
        if (__ldg(a + mid) < v) lo = mid + 1; else hi = mid;
    }
    return lo;
}

__global__ __launch_bounds__(256) void agg_kernel(
    const float4* __restrict__ feat4,
    const float*  __restrict__ affine,
    const int*    __restrict__ src,
    const int*    __restrict__ dst,
    int n_nodes, int n_edges)
{
    int warp = (blockIdx.x * blockDim.x + threadIdx.x) >> 5;
    int lane = threadIdx.x & 31;
    if (warp >= n_nodes) return;

    int lo = lower_bound_i(dst, n_edges, warp);
    int hi = lower_bound_i(dst, n_edges, warp + 1);

    float4 acc = make_float4(0.f, 0.f, 0.f, 0.f);
    for (int e = lo; e < hi; ++e) {
        int   s = __ldg(src + e);
        float a = __ldg(affine + e);
        float4 f = __ldg(feat4 + (size_t)s * (D_FEAT / 4) + lane);
        acc.x = fmaf(f.x, a, acc.x);
        acc.y = fmaf(f.y, a, acc.y);
        acc.z = fmaf(f.z, a, acc.z);
        acc.w = fmaf(f.w, a, acc.w);
    }
    float4* agg4 = reinterpret_cast<float4*>(g_agg);
    agg4[(size_t)warp * (D_FEAT / 4) + lane] = acc;
}

// ---------------------------------------------------------------------------
// Kernel 2: out[M,128] = [feat | agg] @ W[256,128] + b, tiled GEMM with
// packed fma.rn.f32x2 accumulation (2 MACs / issue slot).
// BM=64, BN=128 (full), BK=32; 256 threads; thread = (ty row-group of 8, tx
// col-quad of 4). 16 packed accumulators = 8 rows x 4 cols.
// ---------------------------------------------------------------------------
#define BM 64
#define BK 32
#define TM 8

__device__ __forceinline__ unsigned long long pack2(float a, float b) {
    unsigned long long r;
    asm("mov.b64 %0, {%1, %2};" : "=l"(r) : "f"(a), "f"(b));
    return r;
}
__device__ __forceinline__ void unpack2(unsigned long long v, float& a, float& b) {
    asm("mov.b64 {%0, %1}, %2;" : "=f"(a), "=f"(b) : "l"(v));
}
__device__ __forceinline__ void ffma2(unsigned long long& acc,
                                      unsigned long long x2,
                                      unsigned long long w2) {
    asm("fma.rn.f32x2 %0, %1, %2, %0;" : "+l"(acc) : "l"(x2), "l"(w2));
}

__global__ __launch_bounds__(256) void gemm_kernel(
    const float* __restrict__ feat,
    const float* __restrict__ W,
    const float* __restrict__ bias,
    float*       __restrict__ out,
    int M)
{
    __shared__ float sX[BM][BK];       // 8 KB
    __shared__ float sW[BK][D_FEAT];   // 16 KB

    const int tid = threadIdx.x;
    const int tx  = tid & 31;          // column quad: cols [tx*4, tx*4+4)
    const int ty  = tid >> 5;          // row group:   rows [ty*8, ty*8+8)
    const int m0  = blockIdx.x * BM;

    unsigned long long acc01[TM], acc23[TM];
    const unsigned long long z = pack2(0.f, 0.f);
#pragma unroll
    for (int i = 0; i < TM; ++i) { acc01[i] = z; acc23[i] = z; }

#pragma unroll 1
    for (int kt = 0; kt < K_TOT / BK; ++kt) {
        // --- load X tile [BM x BK]: k < 128 comes from feat, else from g_agg
        const float* xsrc = (kt < 4) ? feat : g_agg;
        const int kc = (kt & 3) * BK;
#pragma unroll
        for (int i = 0; i < 2; ++i) {
            int id = tid + i * 256;            // 0..511
            int r  = id >> 3;                  // 0..63
            int c4 = id & 7;                   // 0..7 (float4 within 32 cols)
            int mr = m0 + r; if (mr >= M) mr = M - 1;   // clamp (store guarded)
            float4 v = __ldg(reinterpret_cast<const float4*>(
                                 xsrc + (size_t)mr * D_FEAT + kc) + c4);
            *reinterpret_cast<float4*>(&sX[r][c4 * 4]) = v;
        }
        // --- load W tile [BK x 128]
#pragma unroll
        for (int i = 0; i < 4; ++i) {
            int id = tid + i * 256;            // 0..1023
            int r  = id >> 5;                  // 0..31
            int c4 = id & 31;                  // 0..31
            float4 v = __ldg(reinterpret_cast<const float4*>(
                                 W + (size_t)(kt * BK + r) * D_FEAT) + c4);
            *reinterpret_cast<float4*>(&sW[r][c4 * 4]) = v;
        }
        __syncthreads();

#pragma unroll
        for (int kk = 0; kk < BK; ++kk) {
            float4 w = *reinterpret_cast<const float4*>(&sW[kk][tx * 4]);
            unsigned long long w01 = pack2(w.x, w.y);
            unsigned long long w23 = pack2(w.z, w.w);
#pragma unroll
            for (int i = 0; i < TM; ++i) {
                float x = sX[ty * TM + i][kk];          // broadcast within warp
                unsigned long long x2 = pack2(x, x);
                ffma2(acc01[i], x2, w01);
                ffma2(acc23[i], x2, w23);
            }
        }
        __syncthreads();
    }

    // --- epilogue: add bias, store
    float4 bv = __ldg(reinterpret_cast<const float4*>(bias) + tx);
#pragma unroll
    for (int i = 0; i < TM; ++i) {
        int mr = m0 + ty * TM + i;
        if (mr < M) {
            float a0, a1, a2, a3;
            unpack2(acc01[i], a0, a1);
            unpack2(acc23[i], a2, a3);
            float4 o = make_float4(a0 + bv.x, a1 + bv.y, a2 + bv.z, a3 + bv.w);
            *reinterpret_cast<float4*>(out + (size_t)mr * D_FEAT + tx * 4) = o;
        }
    }
}

// ---------------------------------------------------------------------------
// Launch
// ---------------------------------------------------------------------------
extern "C" void kernel_launch(void* const* d_in, const int* in_sizes, int n_in,
                              void* d_out, int out_size)
{
    const float* feat   = (const float*)d_in[0];   // [N, 128]
    const float* affine = (const float*)d_in[1];   // [E]
    const int*   src    = (const int*)  d_in[2];   // [E]
    const int*   dst    = (const int*)  d_in[3];   // [E] (sorted)
    const float* W      = (const float*)d_in[4];   // [256, 128]
    const float* bias   = (const float*)d_in[5];   // [128]
    float*       out    = (float*)d_out;           // [N, 128]

    const int n_nodes = in_sizes[0] / D_FEAT;      // 50000
    const int n_edges = in_sizes[1];               // 625000

    // Kernel 1: one warp per node
    {
        int warps   = n_nodes;
        int threads = 256;
        int blocks  = (warps * 32 + threads - 1) / threads;
        agg_kernel<<<blocks, threads>>>(
            reinterpret_cast<const float4*>(feat), affine, src, dst,
            n_nodes, n_edges);
    }
    // Kernel 2: tiled GEMM + bias
    {
        int blocks = (n_nodes + BM - 1) / BM;
        gemm_kernel<<<blocks, 256>>>(feat, W, bias, out, n_nodes);
    }
}

// round 2
// speedup vs baseline: 1.2021x; 1.2021x over previous
#include <cuda_runtime.h>
#include <cstdint>

// Problem constants (match reference setup_inputs)
#define N_NODES 50000
#define D_FEAT  128
#define K_TOT   256      // 2 * D_FEAT
#define N_EDGES 625000

// Scratch (allocation-free rule: __device__ globals)
__device__ float g_agg[(size_t)N_NODES * D_FEAT];
__device__ int   g_row_ptr[N_NODES + 1];

// ---------------------------------------------------------------------------
// Kernel 0: row_ptr[v] = lower_bound(dst, v). One thread per node (+1).
// dst is sorted, so node v's edges are [row_ptr[v], row_ptr[v+1]).
// ---------------------------------------------------------------------------
__global__ __launch_bounds__(256) void rowptr_kernel(
    const int* __restrict__ dst, int n_nodes, int n_edges)
{
    int v = blockIdx.x * blockDim.x + threadIdx.x;
    if (v > n_nodes) return;
    int lo = 0, hi = n_edges;
    while (lo < hi) {
        int mid = (lo + hi) >> 1;
        if (__ldg(dst + mid) < v) lo = mid + 1; else hi = mid;
    }
    g_row_ptr[v] = lo;
}

// ---------------------------------------------------------------------------
// Kernel 1: warp-per-node segmented reduction, edge loop unrolled x4 (MLP=4).
// Each lane owns 4 features (float4). No atomics, no per-warp binary search.
// ---------------------------------------------------------------------------
__global__ __launch_bounds__(256) void agg_kernel(
    const float4* __restrict__ feat4,
    const float*  __restrict__ affine,
    const int*    __restrict__ src,
    int n_nodes)
{
    int warp = (blockIdx.x * blockDim.x + threadIdx.x) >> 5;
    int lane = threadIdx.x & 31;
    if (warp >= n_nodes) return;

    int e  = __ldg(&g_row_ptr[warp]);
    int e1 = __ldg(&g_row_ptr[warp + 1]);

    float4 acc0 = make_float4(0.f, 0.f, 0.f, 0.f);
    float4 acc1 = make_float4(0.f, 0.f, 0.f, 0.f);

    for (; e + 4 <= e1; e += 4) {
        int   s0 = __ldg(src + e + 0), s1 = __ldg(src + e + 1);
        int   s2 = __ldg(src + e + 2), s3 = __ldg(src + e + 3);
        float a0 = __ldg(affine + e + 0), a1 = __ldg(affine + e + 1);
        float a2 = __ldg(affine + e + 2), a3 = __ldg(affine + e + 3);
        float4 f0 = __ldg(feat4 + (size_t)s0 * (D_FEAT / 4) + lane);
        float4 f1 = __ldg(feat4 + (size_t)s1 * (D_FEAT / 4) + lane);
        float4 f2 = __ldg(feat4 + (size_t)s2 * (D_FEAT / 4) + lane);
        float4 f3 = __ldg(feat4 + (size_t)s3 * (D_FEAT / 4) + lane);
        acc0.x = fmaf(f0.x, a0, acc0.x); acc0.y = fmaf(f0.y, a0, acc0.y);
        acc0.z = fmaf(f0.z, a0, acc0.z); acc0.w = fmaf(f0.w, a0, acc0.w);
        acc1.x = fmaf(f1.x, a1, acc1.x); acc1.y = fmaf(f1.y, a1, acc1.y);
        acc1.z = fmaf(f1.z, a1, acc1.z); acc1.w = fmaf(f1.w, a1, acc1.w);
        acc0.x = fmaf(f2.x, a2, acc0.x); acc0.y = fmaf(f2.y, a2, acc0.y);
        acc0.z = fmaf(f2.z, a2, acc0.z); acc0.w = fmaf(f2.w, a2, acc0.w);
        acc1.x = fmaf(f3.x, a3, acc1.x); acc1.y = fmaf(f3.y, a3, acc1.y);
        acc1.z = fmaf(f3.z, a3, acc1.z); acc1.w = fmaf(f3.w, a3, acc1.w);
    }
    for (; e < e1; ++e) {
        int   s = __ldg(src + e);
        float a = __ldg(affine + e);
        float4 f = __ldg(feat4 + (size_t)s * (D_FEAT / 4) + lane);
        acc0.x = fmaf(f.x, a, acc0.x); acc0.y = fmaf(f.y, a, acc0.y);
        acc0.z = fmaf(f.z, a, acc0.z); acc0.w = fmaf(f.w, a, acc0.w);
    }
    float4 r = make_float4(acc0.x + acc1.x, acc0.y + acc1.y,
                           acc0.z + acc1.z, acc0.w + acc1.w);
    reinterpret_cast<float4*>(g_agg)[(size_t)warp * (D_FEAT / 4) + lane] = r;
}

// ---------------------------------------------------------------------------
// Kernel 2: out[M,128] = [feat | agg] @ W[256,128] + b
// BM=64, BN=128(full), BK=16, 256 threads. Accumulators packed along M
// (row pairs) so x-pairs come directly from LDS.128 (no packing MOVs).
// X tile stored TRANSPOSED in smem; W tile double-buffered via cp.async;
// X double-buffered via register prefetch.
// ---------------------------------------------------------------------------
#define BM   64
#define BK   16
#define NT   (K_TOT / BK)   // 16 k-tiles
#define XPAD 4              // keeps 16B alignment, reduces STS conflicts

__device__ __forceinline__ unsigned long long pack2(float a, float b) {
    unsigned long long r;
    asm("mov.b64 %0, {%1, %2};" : "=l"(r) : "f"(a), "f"(b));
    return r;
}
__device__ __forceinline__ void unpack2(unsigned long long v, float& a, float& b) {
    asm("mov.b64 {%0, %1}, %2;" : "=f"(a), "=f"(b) : "l"(v));
}
__device__ __forceinline__ void ffma2(unsigned long long& acc,
                                      unsigned long long x2,
                                      unsigned long long w2) {
    asm("fma.rn.f32x2 %0, %1, %2, %0;" : "+l"(acc) : "l"(x2), "l"(w2));
}
__device__ __forceinline__ void cp_async16(uint32_t smem, const void* gmem) {
    asm volatile("cp.async.cg.shared.global [%0], [%1], 16;\n"
                 :: "r"(smem), "l"(gmem));
}
__device__ __forceinline__ void cp_commit() {
    asm volatile("cp.async.commit_group;\n" ::);
}
template <int N>
__device__ __forceinline__ void cp_wait() {
    asm volatile("cp.async.wait_group %0;\n" :: "n"(N));
}

__global__ __launch_bounds__(256) void gemm_kernel(
    const float* __restrict__ feat,
    const float* __restrict__ W,
    const float* __restrict__ bias,
    float*       __restrict__ out,
    int M)
{
    __shared__ __align__(16) float sXT[2][BK][BM + XPAD]; // transposed X tiles
    __shared__ __align__(16) float sW[2][BK][D_FEAT];

    const int tid = threadIdx.x;
    const int tx  = tid & 31;        // col quad: cols [tx*4, tx*4+4)
    const int ty  = tid >> 5;        // row group: rows [ty*8, ty*8+8)
    const int m0  = blockIdx.x * BM;

    // X loader mapping: thread -> (row m, k-quad kq)
    const int xm  = tid >> 2;        // 0..63
    const int xkq = tid & 3;         // 0..3 (4 k per quad -> BK=16)
    int xmr = m0 + xm; if (xmr >= M) xmr = M - 1;

    // W loader mapping (2 float4 per thread per tile)
    const int wr0 = tid >> 5;              // 0..7
    const int wc0 = tid & 31;              // 0..31
    const int wr1 = 8 + (tid >> 5);

    unsigned long long acc[4][4];    // [row-pair][col]
    const unsigned long long z = pack2(0.f, 0.f);
#pragma unroll
    for (int p = 0; p < 4; ++p)
#pragma unroll
        for (int c = 0; c < 4; ++c) acc[p][c] = z;

    // --- prologue: fetch tile 0
    float4 xv = __ldg(reinterpret_cast<const float4*>(
                          feat + (size_t)xmr * D_FEAT + xkq * 4));
    {
        uint32_t s0 = (uint32_t)__cvta_generic_to_shared(&sW[0][wr0][wc0 * 4]);
        uint32_t s1 = (uint32_t)__cvta_generic_to_shared(&sW[0][wr1][wc0 * 4]);
        cp_async16(s0, W + (size_t)wr0 * D_FEAT + wc0 * 4);
        cp_async16(s1, W + (size_t)wr1 * D_FEAT + wc0 * 4);
        cp_commit();
    }

#pragma unroll 1
    for (int kt = 0; kt < NT; ++kt) {
        const int buf = kt & 1;

        // prefetch next tile
        float4 xn;
        if (kt + 1 < NT) {
            const float* xsrc = ((kt + 1) < 8) ? feat : g_agg;
            const int kc = ((kt + 1) & 7) * BK;
            xn = __ldg(reinterpret_cast<const float4*>(
                           xsrc + (size_t)xmr * D_FEAT + kc + xkq * 4));
            const int nb = buf ^ 1;
            const int kr = (kt + 1) * BK;
            uint32_t s0 = (uint32_t)__cvta_generic_to_shared(&sW[nb][wr0][wc0 * 4]);
            uint32_t s1 = (uint32_t)__cvta_generic_to_shared(&sW[nb][wr1][wc0 * 4]);
            cp_async16(s0, W + (size_t)(kr + wr0) * D_FEAT + wc0 * 4);
            cp_async16(s1, W + (size_t)(kr + wr1) * D_FEAT + wc0 * 4);
            cp_commit();
            cp_wait<1>();
        } else {
            cp_wait<0>();
        }

        // store current X regs transposed
        sXT[buf][xkq * 4 + 0][xm] = xv.x;
        sXT[buf][xkq * 4 + 1][xm] = xv.y;
        sXT[buf][xkq * 4 + 2][xm] = xv.z;
        sXT[buf][xkq * 4 + 3][xm] = xv.w;
        __syncthreads();

        // compute
#pragma unroll
        for (int kk = 0; kk < BK; ++kk) {
            float4 w = *reinterpret_cast<const float4*>(&sW[buf][kk][tx * 4]);
            unsigned long long w0 = pack2(w.x, w.x);
            unsigned long long w1 = pack2(w.y, w.y);
            unsigned long long w2 = pack2(w.z, w.z);
            unsigned long long w3 = pack2(w.w, w.w);
            ulonglong2 xab = *reinterpret_cast<const ulonglong2*>(&sXT[buf][kk][ty * 8]);
            ulonglong2 xcd = *reinterpret_cast<const ulonglong2*>(&sXT[buf][kk][ty * 8 + 4]);
            ffma2(acc[0][0], xab.x, w0); ffma2(acc[0][1], xab.x, w1);
            ffma2(acc[0][2], xab.x, w2); ffma2(acc[0][3], xab.x, w3);
            ffma2(acc[1][0], xab.y, w0); ffma2(acc[1][1], xab.y, w1);
            ffma2(acc[1][2], xab.y, w2); ffma2(acc[1][3], xab.y, w3);
            ffma2(acc[2][0], xcd.x, w0); ffma2(acc[2][1], xcd.x, w1);
            ffma2(acc[2][2], xcd.x, w2); ffma2(acc[2][3], xcd.x, w3);
            ffma2(acc[3][0], xcd.y, w0); ffma2(acc[3][1], xcd.y, w1);
            ffma2(acc[3][2], xcd.y, w2); ffma2(acc[3][3], xcd.y, w3);
        }
        __syncthreads();
        xv = xn;
    }

    // --- epilogue: bias + store (row pair p -> rows ty*8+2p, ty*8+2p+1)
    float4 bv = __ldg(reinterpret_cast<const float4*>(bias) + tx);
#pragma unroll
    for (int p = 0; p < 4; ++p) {
        float lo0, hi0, lo1, hi1, lo2, hi2, lo3, hi3;
        unpack2(acc[p][0], lo0, hi0);
        unpack2(acc[p][1], lo1, hi1);
        unpack2(acc[p][2], lo2, hi2);
        unpack2(acc[p][3], lo3, hi3);
        int r0 = m0 + ty * 8 + 2 * p;
        int r1 = r0 + 1;
        if (r0 < M) {
            float4 o = make_float4(lo0 + bv.x, lo1 + bv.y, lo2 + bv.z, lo3 + bv.w);
            *reinterpret_cast<float4*>(out + (size_t)r0 * D_FEAT + tx * 4) = o;
        }
        if (r1 < M) {
            float4 o = make_float4(hi0 + bv.x, hi1 + bv.y, hi2 + bv.z, hi3 + bv.w);
            *reinterpret_cast<float4*>(out + (size_t)r1 * D_FEAT + tx * 4) = o;
        }
    }
}

// ---------------------------------------------------------------------------
// Launch
// ---------------------------------------------------------------------------
extern "C" void kernel_launch(void* const* d_in, const int* in_sizes, int n_in,
                              void* d_out, int out_size)
{
    const float* feat   = (const float*)d_in[0];   // [N, 128]
    const float* affine = (const float*)d_in[1];   // [E]
    const int*   src    = (const int*)  d_in[2];   // [E]
    const int*   dst    = (const int*)  d_in[3];   // [E] (sorted)
    const float* W      = (const float*)d_in[4];   // [256, 128]
    const float* bias   = (const float*)d_in[5];   // [128]
    float*       out    = (float*)d_out;           // [N, 128]

    const int n_nodes = in_sizes[0] / D_FEAT;
    const int n_edges = in_sizes[1];

    // Kernel 0: row offsets
    rowptr_kernel<<<(n_nodes + 1 + 255) / 256, 256>>>(dst, n_nodes, n_edges);

    // Kernel 1: warp-per-node aggregation
    {
        int blocks = (n_nodes * 32 + 255) / 256;
        agg_kernel<<<blocks, 256>>>(
            reinterpret_cast<const float4*>(feat), affine, src, n_nodes);
    }
    // Kernel 2: fused GEMM + bias
    gemm_kernel<<<(n_nodes + BM - 1) / BM, 256>>>(feat, W, bias, out, n_nodes);
}

// round 5
// speedup vs baseline: 1.7255x; 1.4354x over previous
#include <cuda_runtime.h>
#include <cuda_bf16.h>
#include <cstdint>

// Problem constants
#define N_NODES 50000
#define D_FEAT  128
#define K_TOT   256
#define N_EDGES 625000

__device__ float g_agg[(size_t)N_NODES * D_FEAT];
__device__ int   g_row_ptr[N_NODES + 1];

// ===========================================================================
// Helpers
// ===========================================================================
__device__ __forceinline__ uint32_t smem_u32(const void* p) {
    uint32_t a;
    asm("{ .reg .u64 t; cvta.to.shared.u64 t, %1; cvt.u32.u64 %0, t; }"
        : "=r"(a) : "l"(p));
    return a;
}
// Swizzle<3,4,3>: XOR 16B-chunk index (bits 4-6) with row%8 (bits 7-9).
#define SWZ128(off) ((off) ^ (((off) >> 3) & 0x70))

__device__ __forceinline__ uint32_t pack_bf16x2(float a, float b) {
    __nv_bfloat162 h = __floats2bfloat162_rn(a, b);
    return *reinterpret_cast<uint32_t*>(&h);
}

__device__ __forceinline__ void ldsm_x4(uint32_t r[4], uint32_t addr) {
    asm volatile("ldmatrix.sync.aligned.m8n8.x4.shared.b16 {%0,%1,%2,%3}, [%4];"
                 : "=r"(r[0]), "=r"(r[1]), "=r"(r[2]), "=r"(r[3]) : "r"(addr));
}
__device__ __forceinline__ void mma_bf16(float c[4], const uint32_t a[4],
                                         uint32_t b0, uint32_t b1) {
    asm volatile(
        "mma.sync.aligned.m16n8k16.row.col.f32.bf16.bf16.f32 "
        "{%0,%1,%2,%3}, {%4,%5,%6,%7}, {%8,%9}, {%0,%1,%2,%3};"
        : "+f"(c[0]), "+f"(c[1]), "+f"(c[2]), "+f"(c[3])
        : "r"(a[0]), "r"(a[1]), "r"(a[2]), "r"(a[3]), "r"(b0), "r"(b1));
}

// ===========================================================================
// Kernel 0: row_ptr via edge scan (coalesced, no binary search).
// ===========================================================================
__global__ __launch_bounds__(256) void rowptr_kernel(
    const int* __restrict__ dst, int n_nodes, int n_edges)
{
    int e = blockIdx.x * blockDim.x + threadIdx.x;
    if (e >= n_edges) return;
    int d  = __ldg(dst + e);
    int dp = (e == 0) ? -1 : __ldg(dst + e - 1);
    for (int v = dp + 1; v <= d; ++v) g_row_ptr[v] = e;
    if (e == n_edges - 1)
        for (int v = d + 1; v <= n_nodes; ++v) g_row_ptr[v] = n_edges;
}

// ===========================================================================
// Kernel 1: warp-per-node segmented reduction.
// ===========================================================================
__global__ __launch_bounds__(256) void agg_kernel(
    const float4* __restrict__ feat4,
    const float*  __restrict__ affine,
    const int*    __restrict__ src,
    int n_nodes)
{
    int warp = (blockIdx.x * blockDim.x + threadIdx.x) >> 5;
    int lane = threadIdx.x & 31;
    if (warp >= n_nodes) return;

    int e  = __ldg(&g_row_ptr[warp]);
    int e1 = __ldg(&g_row_ptr[warp + 1]);

    float4 acc0 = make_float4(0.f, 0.f, 0.f, 0.f);
    float4 acc1 = make_float4(0.f, 0.f, 0.f, 0.f);

    for (; e + 4 <= e1; e += 4) {
        int   s0 = __ldg(src + e + 0), s1 = __ldg(src + e + 1);
        int   s2 = __ldg(src + e + 2), s3 = __ldg(src + e + 3);
        float a0 = __ldg(affine + e + 0), a1 = __ldg(affine + e + 1);
        float a2 = __ldg(affine + e + 2), a3 = __ldg(affine + e + 3);
        float4 f0 = __ldg(feat4 + (size_t)s0 * 32 + lane);
        float4 f1 = __ldg(feat4 + (size_t)s1 * 32 + lane);
        float4 f2 = __ldg(feat4 + (size_t)s2 * 32 + lane);
        float4 f3 = __ldg(feat4 + (size_t)s3 * 32 + lane);
        acc0.x = fmaf(f0.x, a0, acc0.x); acc0.y = fmaf(f0.y, a0, acc0.y);
        acc0.z = fmaf(f0.z, a0, acc0.z); acc0.w = fmaf(f0.w, a0, acc0.w);
        acc1.x = fmaf(f1.x, a1, acc1.x); acc1.y = fmaf(f1.y, a1, acc1.y);
        acc1.z = fmaf(f1.z, a1, acc1.z); acc1.w = fmaf(f1.w, a1, acc1.w);
        acc0.x = fmaf(f2.x, a2, acc0.x); acc0.y = fmaf(f2.y, a2, acc0.y);
        acc0.z = fmaf(f2.z, a2, acc0.z); acc0.w = fmaf(f2.w, a2, acc0.w);
        acc1.x = fmaf(f3.x, a3, acc1.x); acc1.y = fmaf(f3.y, a3, acc1.y);
        acc1.z = fmaf(f3.z, a3, acc1.z); acc1.w = fmaf(f3.w, a3, acc1.w);
    }
    for (; e < e1; ++e) {
        int   s = __ldg(src + e);
        float a = __ldg(affine + e);
        float4 f = __ldg(feat4 + (size_t)s * 32 + lane);
        acc0.x = fmaf(f.x, a, acc0.x); acc0.y = fmaf(f.y, a, acc0.y);
        acc0.z = fmaf(f.z, a, acc0.z); acc0.w = fmaf(f.w, a, acc0.w);
    }
    float4 r = make_float4(acc0.x + acc1.x, acc0.y + acc1.y,
                           acc0.z + acc1.z, acc0.w + acc1.w);
    reinterpret_cast<float4*>(g_agg)[(size_t)warp * 32 + lane] = r;
}

// ===========================================================================
// Kernel 2: split-bf16 GEMM on HMMA (mma.sync m16n8k16, base-ISA).
// out[M,128] = [feat | agg] @ W[256,128] + b via AhBh + AhBl + AlBh.
// CTA: 128 rows x 128 cols, 8 warps (4m x 2n grid), warp tile 32m x 64n.
// K processed in 4 tiles of 64. A stored [row][k] bf16 SW128; B stored
// [n][k] bf16 SW128 (transposed from W), both read with ldmatrix.x4.
// ===========================================================================
#define MT 128
#define SM_XH 0
#define SM_XL 16384
#define SM_WH 32768
#define SM_WL 49152
#define SM_GEMM_TOTAL 65536

__global__ __launch_bounds__(256) void gemm_kernel(
    const float* __restrict__ feat,
    const float* __restrict__ W,
    const float* __restrict__ bias,
    float*       __restrict__ out,
    int M)
{
    extern __shared__ char smem[];
    const uint32_t sb = smem_u32(smem);
    const int tid  = threadIdx.x;
    const int lane = tid & 31;
    const int wid  = tid >> 5;
    const int wm   = wid >> 1;       // 0..3: rows [wm*32, wm*32+32)
    const int wn   = wid & 1;        // 0..1: cols [wn*64, wn*64+64)
    const int m0   = blockIdx.x * MT;

    float c[2][8][4];
#pragma unroll
    for (int t = 0; t < 2; ++t)
#pragma unroll
        for (int j = 0; j < 8; ++j)
#pragma unroll
            for (int q = 0; q < 4; ++q) c[t][j][q] = 0.f;

#pragma unroll 1
    for (int kt = 0; kt < 4; ++kt) {
        // ---- convert X tile: 128 rows x 64 k (fp32 -> bf16 hi/lo) ----
        const float* xsrc = (kt < 2) ? feat : g_agg;
        const int kc = (kt & 1) * 64;
#pragma unroll
        for (int i = 0; i < 8; ++i) {
            int idx = i * 256 + tid;       // 0..2047
            int row = idx >> 4;            // 0..127
            int c4  = idx & 15;            // float4 within 64 k
            int mr  = m0 + row; if (mr >= M) mr = M - 1;
            float4 v = __ldg(reinterpret_cast<const float4*>(
                                 xsrc + (size_t)mr * D_FEAT + kc) + c4);
            float hx = __bfloat162float(__float2bfloat16(v.x));
            float hy = __bfloat162float(__float2bfloat16(v.y));
            float hz = __bfloat162float(__float2bfloat16(v.z));
            float hw = __bfloat162float(__float2bfloat16(v.w));
            uint2 hi = make_uint2(pack_bf16x2(v.x, v.y), pack_bf16x2(v.z, v.w));
            uint2 lo = make_uint2(pack_bf16x2(v.x - hx, v.y - hy),
                                  pack_bf16x2(v.z - hz, v.w - hw));
            uint32_t off = SWZ128((uint32_t)(row * 128 + c4 * 8));
            *reinterpret_cast<uint2*>(smem + SM_XH + off) = hi;
            *reinterpret_cast<uint2*>(smem + SM_XL + off) = lo;
        }
        // ---- convert W tile -> B[n][k]: 128 n x 64 k ----
#pragma unroll
        for (int i = 0; i < 8; ++i) {
            int idx = i * 256 + tid;       // 0..2047
            int n   = idx & 127;
            int kq  = idx >> 7;            // 0..15 (4 k each)
            float w[4], h[4];
#pragma unroll
            for (int j = 0; j < 4; ++j) {
                w[j] = __ldg(W + (size_t)(kt * 64 + kq * 4 + j) * D_FEAT + n);
                h[j] = __bfloat162float(__float2bfloat16(w[j]));
            }
            uint2 hi = make_uint2(pack_bf16x2(w[0], w[1]), pack_bf16x2(w[2], w[3]));
            uint2 lo = make_uint2(pack_bf16x2(w[0] - h[0], w[1] - h[1]),
                                  pack_bf16x2(w[2] - h[2], w[3] - h[3]));
            uint32_t off = SWZ128((uint32_t)(n * 128 + kq * 8));
            *reinterpret_cast<uint2*>(smem + SM_WH + off) = hi;
            *reinterpret_cast<uint2*>(smem + SM_WL + off) = lo;
        }
        __syncthreads();

        // ---- compute: 4 k-steps of 16 ----
#pragma unroll
        for (int ks = 0; ks < 4; ++ks) {
            // A fragments (hi & lo), 2 m-tiles of 16
            uint32_t ah[2][4], al[2][4];
#pragma unroll
            for (int t = 0; t < 2; ++t) {
                int row = wm * 32 + t * 16 + (lane & 15);
                uint32_t off = SWZ128((uint32_t)(row * 128 + ks * 32 + (lane >> 4) * 16));
                ldsm_x4(ah[t], sb + SM_XH + off);
                ldsm_x4(al[t], sb + SM_XL + off);
            }
            // B address (x4 covers n-tile pair: 16 n x 16 k)
            int bg = lane >> 3;            // matrix id 0..3
            int bn_in = ((bg >> 1) << 3) + (lane & 7);   // 0..15
            int bk    = ks * 32 + (bg & 1) * 16;

            uint32_t b[4][4];
            // pass 1+2: Bh -> AhBh, AlBh
#pragma unroll
            for (int j = 0; j < 4; ++j) {
                int n = wn * 64 + j * 16 + bn_in;
                uint32_t off = SWZ128((uint32_t)(n * 128 + bk));
                ldsm_x4(b[j], sb + SM_WH + off);
            }
#pragma unroll
            for (int t = 0; t < 2; ++t)
#pragma unroll
                for (int j = 0; j < 4; ++j) {
                    mma_bf16(c[t][2 * j + 0], ah[t], b[j][0], b[j][1]);
                    mma_bf16(c[t][2 * j + 1], ah[t], b[j][2], b[j][3]);
                    mma_bf16(c[t][2 * j + 0], al[t], b[j][0], b[j][1]);
                    mma_bf16(c[t][2 * j + 1], al[t], b[j][2], b[j][3]);
                }
            // pass 3: Bl -> AhBl
#pragma unroll
            for (int j = 0; j < 4; ++j) {
                int n = wn * 64 + j * 16 + bn_in;
                uint32_t off = SWZ128((uint32_t)(n * 128 + bk));
                ldsm_x4(b[j], sb + SM_WL + off);
            }
#pragma unroll
            for (int t = 0; t < 2; ++t)
#pragma unroll
                for (int j = 0; j < 4; ++j) {
                    mma_bf16(c[t][2 * j + 0], ah[t], b[j][0], b[j][1]);
                    mma_bf16(c[t][2 * j + 1], ah[t], b[j][2], b[j][3]);
                }
        }
        __syncthreads();
    }

    // ---- epilogue: bias + store ----
#pragma unroll
    for (int t = 0; t < 2; ++t) {
#pragma unroll
        for (int j = 0; j < 8; ++j) {
            int col = wn * 64 + j * 8 + (lane & 3) * 2;
            float b0 = __ldg(bias + col);
            float b1 = __ldg(bias + col + 1);
            int r0 = m0 + wm * 32 + t * 16 + (lane >> 2);
            int r1 = r0 + 8;
            if (r0 < M) {
                float2 o = make_float2(c[t][j][0] + b0, c[t][j][1] + b1);
                *reinterpret_cast<float2*>(out + (size_t)r0 * D_FEAT + col) = o;
            }
            if (r1 < M) {
                float2 o = make_float2(c[t][j][2] + b0, c[t][j][3] + b1);
                *reinterpret_cast<float2*>(out + (size_t)r1 * D_FEAT + col) = o;
            }
        }
    }
}

// ===========================================================================
// Launch
// ===========================================================================
extern "C" void kernel_launch(void* const* d_in, const int* in_sizes, int n_in,
                              void* d_out, int out_size)
{
    const float* feat   = (const float*)d_in[0];
    const float* affine = (const float*)d_in[1];
    const int*   src    = (const int*)  d_in[2];
    const int*   dst    = (const int*)  d_in[3];
    const float* W      = (const float*)d_in[4];
    const float* bias   = (const float*)d_in[5];
    float*       out    = (float*)d_out;

    const int n_nodes = in_sizes[0] / D_FEAT;
    const int n_edges = in_sizes[1];

    cudaFuncSetAttribute(gemm_kernel,
                         cudaFuncAttributeMaxDynamicSharedMemorySize, SM_GEMM_TOTAL);

    rowptr_kernel<<<(n_edges + 255) / 256, 256>>>(dst, n_nodes, n_edges);

    agg_kernel<<<(n_nodes * 32 + 255) / 256, 256>>>(
        reinterpret_cast<const float4*>(feat), affine, src, n_nodes);

    gemm_kernel<<<(n_nodes + MT - 1) / MT, 256, SM_GEMM_TOTAL>>>(
        feat, W, bias, out, n_nodes);
}

// round 6
// speedup vs baseline: 1.8541x; 1.0745x over previous
#include <cuda_runtime.h>
#include <cuda_bf16.h>
#include <cstdint>

// Problem constants
#define N_NODES 50000
#define D_FEAT  128
#define K_TOT   256
#define MT      128
#define NCTA    ((N_NODES + MT - 1) / MT)   // 391
#define TILE_B  16384                        // one [128 x 64] bf16 tile image

// Scratch (__device__ globals; zero-initialized at load)
__device__ __align__(16) uint8_t g_aggh_img[(size_t)NCTA * 2 * TILE_B];
__device__ __align__(16) uint8_t g_aggl_img[(size_t)NCTA * 2 * TILE_B];
__device__ __align__(16) uint8_t g_Wh_img[4 * TILE_B];
__device__ __align__(16) uint8_t g_Wl_img[4 * TILE_B];
__device__ int g_row_ptr[N_NODES + 1];

// ===========================================================================
// Helpers
// ===========================================================================
__device__ __forceinline__ uint32_t smem_u32(const void* p) {
    uint32_t a;
    asm("{ .reg .u64 t; cvta.to.shared.u64 t, %1; cvt.u32.u64 %0, t; }"
        : "=r"(a) : "l"(p));
    return a;
}
#define SWZ128(off) ((off) ^ (((off) >> 3) & 0x70))

__device__ __forceinline__ uint32_t pack_bf16x2(float a, float b) {
    __nv_bfloat162 h = __floats2bfloat162_rn(a, b);
    return *reinterpret_cast<uint32_t*>(&h);
}
__device__ __forceinline__ void ldsm_x4(uint32_t r[4], uint32_t addr) {
    asm volatile("ldmatrix.sync.aligned.m8n8.x4.shared.b16 {%0,%1,%2,%3}, [%4];"
                 : "=r"(r[0]), "=r"(r[1]), "=r"(r[2]), "=r"(r[3]) : "r"(addr));
}
__device__ __forceinline__ void mma_bf16(float c[4], const uint32_t a[4],
                                         uint32_t b0, uint32_t b1) {
    asm volatile(
        "mma.sync.aligned.m16n8k16.row.col.f32.bf16.bf16.f32 "
        "{%0,%1,%2,%3}, {%4,%5,%6,%7}, {%8,%9}, {%0,%1,%2,%3};"
        : "+f"(c[0]), "+f"(c[1]), "+f"(c[2]), "+f"(c[3])
        : "r"(a[0]), "r"(a[1]), "r"(a[2]), "r"(a[3]), "r"(b0), "r"(b1));
}
__device__ __forceinline__ void cp_async16(uint32_t smem, const void* gmem) {
    asm volatile("cp.async.cg.shared.global [%0], [%1], 16;\n"
                 :: "r"(smem), "l"(gmem));
}
__device__ __forceinline__ void cp_commit() {
    asm volatile("cp.async.commit_group;\n" ::);
}
template <int N>
__device__ __forceinline__ void cp_wait() {
    asm volatile("cp.async.wait_group %0;\n" :: "n"(N));
}

// ===========================================================================
// Kernel P: precompute W -> bf16 hi/lo pre-swizzled tile images (tiny).
// Tile kt holds B[n][kc] for k in [kt*64, kt*64+64), offset n*128 + kc*2, SW128.
// ===========================================================================
__global__ __launch_bounds__(256) void wprep_kernel(const float* __restrict__ W)
{
    for (int idx = blockIdx.x * 256 + threadIdx.x; idx < K_TOT * D_FEAT;
         idx += gridDim.x * 256) {
        int n = idx & 127;
        int k = idx >> 7;                  // 0..255
        float w = __ldg(W + (size_t)k * D_FEAT + n);
        __nv_bfloat16 h = __float2bfloat16(w);
        __nv_bfloat16 l = __float2bfloat16(w - __bfloat162float(h));
        int kt = k >> 6;
        int kc = k & 63;
        uint32_t off = SWZ128((uint32_t)(n * 128 + kc * 2));
        *reinterpret_cast<__nv_bfloat16*>(g_Wh_img + kt * TILE_B + off) = h;
        *reinterpret_cast<__nv_bfloat16*>(g_Wl_img + kt * TILE_B + off) = l;
    }
}

// ===========================================================================
// Kernel 0: row_ptr via vectorized edge scan (4 edges/thread).
// ===========================================================================
__global__ __launch_bounds__(256) void rowptr_kernel(
    const int* __restrict__ dst, int n_nodes, int n_edges)
{
    int e4 = blockIdx.x * blockDim.x + threadIdx.x;
    int e0 = e4 * 4;
    if (e0 >= n_edges) return;
    int v0, v1, v2, v3;
    if (e0 + 3 < n_edges) {
        int4 d = __ldg(reinterpret_cast<const int4*>(dst) + e4);
        v0 = d.x; v1 = d.y; v2 = d.z; v3 = d.w;
    } else {
        v0 = __ldg(dst + e0);
        v1 = (e0 + 1 < n_edges) ? __ldg(dst + e0 + 1) : v0;
        v2 = (e0 + 2 < n_edges) ? __ldg(dst + e0 + 2) : v1;
        v3 = (e0 + 3 < n_edges) ? __ldg(dst + e0 + 3) : v2;
    }
    int dp = (e0 == 0) ? -1 : __ldg(dst + e0 - 1);
    int vals[5] = {dp, v0, v1, v2, v3};
#pragma unroll
    for (int j = 0; j < 4; ++j)
        if (e0 + j < n_edges)
            for (int v = vals[j] + 1; v <= vals[j + 1]; ++v)
                g_row_ptr[v] = e0 + j;
    if (e0 + 4 >= n_edges) {
        int last = vals[4 - (e0 + 4 - n_edges)];
        for (int v = last + 1; v <= n_nodes; ++v) g_row_ptr[v] = n_edges;
    }
}

// ===========================================================================
// Kernel 1: warp-per-node segmented reduction; emits bf16 hi/lo pre-swizzled
// tile-image rows directly (ready for cp.async into the GEMM's smem).
// ===========================================================================
__global__ __launch_bounds__(256) void agg_kernel(
    const float4* __restrict__ feat4,
    const float*  __restrict__ affine,
    const int*    __restrict__ src,
    int n_nodes)
{
    int warp = (blockIdx.x * blockDim.x + threadIdx.x) >> 5;
    int lane = threadIdx.x & 31;
    if (warp >= n_nodes) return;

    int e  = __ldg(&g_row_ptr[warp]);
    int e1 = __ldg(&g_row_ptr[warp + 1]);

    float4 acc0 = make_float4(0.f, 0.f, 0.f, 0.f);
    float4 acc1 = make_float4(0.f, 0.f, 0.f, 0.f);

    for (; e + 4 <= e1; e += 4) {
        int   s0 = __ldg(src + e + 0), s1 = __ldg(src + e + 1);
        int   s2 = __ldg(src + e + 2), s3 = __ldg(src + e + 3);
        float a0 = __ldg(affine + e + 0), a1 = __ldg(affine + e + 1);
        float a2 = __ldg(affine + e + 2), a3 = __ldg(affine + e + 3);
        float4 f0 = __ldg(feat4 + (size_t)s0 * 32 + lane);
        float4 f1 = __ldg(feat4 + (size_t)s1 * 32 + lane);
        float4 f2 = __ldg(feat4 + (size_t)s2 * 32 + lane);
        float4 f3 = __ldg(feat4 + (size_t)s3 * 32 + lane);
        acc0.x = fmaf(f0.x, a0, acc0.x); acc0.y = fmaf(f0.y, a0, acc0.y);
        acc0.z = fmaf(f0.z, a0, acc0.z); acc0.w = fmaf(f0.w, a0, acc0.w);
        acc1.x = fmaf(f1.x, a1, acc1.x); acc1.y = fmaf(f1.y, a1, acc1.y);
        acc1.z = fmaf(f1.z, a1, acc1.z); acc1.w = fmaf(f1.w, a1, acc1.w);
        acc0.x = fmaf(f2.x, a2, acc0.x); acc0.y = fmaf(f2.y, a2, acc0.y);
        acc0.z = fmaf(f2.z, a2, acc0.z); acc0.w = fmaf(f2.w, a2, acc0.w);
        acc1.x = fmaf(f3.x, a3, acc1.x); acc1.y = fmaf(f3.y, a3, acc1.y);
        acc1.z = fmaf(f3.z, a3, acc1.z); acc1.w = fmaf(f3.w, a3, acc1.w);
    }
    for (; e < e1; ++e) {
        int   s = __ldg(src + e);
        float a = __ldg(affine + e);
        float4 f = __ldg(feat4 + (size_t)s * 32 + lane);
        acc0.x = fmaf(f.x, a, acc0.x); acc0.y = fmaf(f.y, a, acc0.y);
        acc0.z = fmaf(f.z, a, acc0.z); acc0.w = fmaf(f.w, a, acc0.w);
    }
    float4 r = make_float4(acc0.x + acc1.x, acc0.y + acc1.y,
                           acc0.z + acc1.z, acc0.w + acc1.w);

    // hi/lo split + pre-swizzled image write
    float hx = __bfloat162float(__float2bfloat16(r.x));
    float hy = __bfloat162float(__float2bfloat16(r.y));
    float hz = __bfloat162float(__float2bfloat16(r.z));
    float hw = __bfloat162float(__float2bfloat16(r.w));
    uint2 hi = make_uint2(pack_bf16x2(r.x, r.y), pack_bf16x2(r.z, r.w));
    uint2 lo = make_uint2(pack_bf16x2(r.x - hx, r.y - hy),
                          pack_bf16x2(r.z - hz, r.w - hw));

    int b   = warp >> 7;          // gemm CTA
    int row = warp & 127;
    int kl  = lane * 4;           // agg k index 0..124
    int t   = kl >> 6;            // half-tile 0/1 -> kt 2/3
    int kc  = kl & 63;
    uint32_t off  = SWZ128((uint32_t)(row * 128 + kc * 2));
    size_t   base = ((size_t)b * 2 + t) * TILE_B;
    *reinterpret_cast<uint2*>(g_aggh_img + base + off) = hi;
    *reinterpret_cast<uint2*>(g_aggl_img + base + off) = lo;
}

// ===========================================================================
// Kernel 2: split-bf16 HMMA GEMM.
// smem: all 4 W tile pairs (128 KB) + agg X tiles kt2/3 (64 KB) prefetched
// via cp.async; feat tiles kt0/1 converted inline into a reused buffer.
// ===========================================================================
#define SM_W   0                       // 4 * (16K hi + 16K lo) = 131072
#define SM_XA  131072                  // 2 * (16K hi + 16K lo) = 65536
#define SM_XF  196608                  // 16K hi + 16K lo = 32768
#define SM_TOTAL 229376

__device__ __forceinline__ void mma_tile(
    uint32_t xh, uint32_t xl, uint32_t wh, uint32_t wl,
    float c[2][8][4], int lane, int wm, int wn)
{
#pragma unroll
    for (int ks = 0; ks < 4; ++ks) {
        uint32_t ah[2][4], al[2][4];
#pragma unroll
        for (int t = 0; t < 2; ++t) {
            int row = wm * 32 + t * 16 + (lane & 15);
            uint32_t off = SWZ128((uint32_t)(row * 128 + ks * 32 + (lane >> 4) * 16));
            ldsm_x4(ah[t], xh + off);
            ldsm_x4(al[t], xl + off);
        }
        int bg    = lane >> 3;
        int bn_in = ((bg >> 1) << 3) + (lane & 7);
        int bk    = ks * 32 + (bg & 1) * 16;

        uint32_t b[4][4];
#pragma unroll
        for (int j = 0; j < 4; ++j) {
            int n = wn * 64 + j * 16 + bn_in;
            ldsm_x4(b[j], wh + SWZ128((uint32_t)(n * 128 + bk)));
        }
#pragma unroll
        for (int t = 0; t < 2; ++t)
#pragma unroll
            for (int j = 0; j < 4; ++j) {
                mma_bf16(c[t][2 * j + 0], ah[t], b[j][0], b[j][1]);
                mma_bf16(c[t][2 * j + 1], ah[t], b[j][2], b[j][3]);
                mma_bf16(c[t][2 * j + 0], al[t], b[j][0], b[j][1]);
                mma_bf16(c[t][2 * j + 1], al[t], b[j][2], b[j][3]);
            }
#pragma unroll
        for (int j = 0; j < 4; ++j) {
            int n = wn * 64 + j * 16 + bn_in;
            ldsm_x4(b[j], wl + SWZ128((uint32_t)(n * 128 + bk)));
        }
#pragma unroll
        for (int t = 0; t < 2; ++t)
#pragma unroll
            for (int j = 0; j < 4; ++j) {
                mma_bf16(c[t][2 * j + 0], ah[t], b[j][0], b[j][1]);
                mma_bf16(c[t][2 * j + 1], ah[t], b[j][2], b[j][3]);
            }
    }
}

__global__ __launch_bounds__(256) void gemm_kernel(
    const float* __restrict__ feat,
    const float* __restrict__ bias,
    float*       __restrict__ out,
    int M)
{
    extern __shared__ char smem[];
    const uint32_t sb = smem_u32(smem);
    const int tid  = threadIdx.x;
    const int lane = tid & 31;
    const int wid  = tid >> 5;
    const int wm   = wid >> 1;
    const int wn   = wid & 1;
    const int m0   = blockIdx.x * MT;
    const int b    = blockIdx.x;

    // ---- prologue: prefetch all W tiles + agg X tiles; 4 commit groups ----
#pragma unroll
    for (int kt = 0; kt < 4; ++kt) {
#pragma unroll
        for (int j = 0; j < 4; ++j) {
            uint32_t o = (uint32_t)(j * 256 + tid) * 16;
            cp_async16(sb + SM_W + kt * 32768 + o,         g_Wh_img + kt * TILE_B + o);
            cp_async16(sb + SM_W + kt * 32768 + 16384 + o, g_Wl_img + kt * TILE_B + o);
        }
        if (kt >= 2) {
            int t = kt - 2;
            size_t base = ((size_t)b * 2 + t) * TILE_B;
#pragma unroll
            for (int j = 0; j < 4; ++j) {
                uint32_t o = (uint32_t)(j * 256 + tid) * 16;
                cp_async16(sb + SM_XA + t * 32768 + o,         g_aggh_img + base + o);
                cp_async16(sb + SM_XA + t * 32768 + 16384 + o, g_aggl_img + base + o);
            }
        }
        cp_commit();
    }

    float c[2][8][4];
#pragma unroll
    for (int t = 0; t < 2; ++t)
#pragma unroll
        for (int j = 0; j < 8; ++j)
#pragma unroll
            for (int q = 0; q < 4; ++q) c[t][j][q] = 0.f;

    // ---- kt0 / kt1: convert feat inline into reused XF buffer ----
#pragma unroll 1
    for (int kt = 0; kt < 2; ++kt) {
        if (kt == 1) __syncthreads();      // protect XF overwrite
        const int kc = kt * 64;
#pragma unroll
        for (int i = 0; i < 8; ++i) {
            int idx = i * 256 + tid;
            int row = idx >> 4;
            int c4  = idx & 15;
            int mr  = m0 + row; if (mr >= M) mr = M - 1;
            float4 v = __ldg(reinterpret_cast<const float4*>(
                                 feat + (size_t)mr * D_FEAT + kc) + c4);
            float hx = __bfloat162float(__float2bfloat16(v.x));
            float hy = __bfloat162float(__float2bfloat16(v.y));
            float hz = __bfloat162float(__float2bfloat16(v.z));
            float hw = __bfloat162float(__float2bfloat16(v.w));
            uint2 hi = make_uint2(pack_bf16x2(v.x, v.y), pack_bf16x2(v.z, v.w));
            uint2 lo = make_uint2(pack_bf16x2(v.x - hx, v.y - hy),
                                  pack_bf16x2(v.z - hz, v.w - hw));
            uint32_t off = SWZ128((uint32_t)(row * 128 + c4 * 8));
            *reinterpret_cast<uint2*>(smem + SM_XF + off) = hi;
            *reinterpret_cast<uint2*>(smem + SM_XF + 16384 + off) = lo;
        }
        if (kt == 0) cp_wait<3>(); else cp_wait<2>();
        __syncthreads();
        mma_tile(sb + SM_XF, sb + SM_XF + 16384,
                 sb + SM_W + kt * 32768, sb + SM_W + kt * 32768 + 16384,
                 c, lane, wm, wn);
    }
    // ---- kt2 / kt3: X from prefetched agg images ----
    cp_wait<0>();
    __syncthreads();
#pragma unroll
    for (int t = 0; t < 2; ++t) {
        int kt = 2 + t;
        mma_tile(sb + SM_XA + t * 32768, sb + SM_XA + t * 32768 + 16384,
                 sb + SM_W + kt * 32768, sb + SM_W + kt * 32768 + 16384,
                 c, lane, wm, wn);
    }

    // ---- epilogue: bias + store ----
#pragma unroll
    for (int t = 0; t < 2; ++t) {
#pragma unroll
        for (int j = 0; j < 8; ++j) {
            int col = wn * 64 + j * 8 + (lane & 3) * 2;
            float b0 = __ldg(bias + col);
            float b1 = __ldg(bias + col + 1);
            int r0 = m0 + wm * 32 + t * 16 + (lane >> 2);
            int r1 = r0 + 8;
            if (r0 < M) {
                float2 o = make_float2(c[t][j][0] + b0, c[t][j][1] + b1);
                *reinterpret_cast<float2*>(out + (size_t)r0 * D_FEAT + col) = o;
            }
            if (r1 < M) {
                float2 o = make_float2(c[t][j][2] + b0, c[t][j][3] + b1);
                *reinterpret_cast<float2*>(out + (size_t)r1 * D_FEAT + col) = o;
            }
        }
    }
}

// ===========================================================================
// Launch
// ===========================================================================
extern "C" void kernel_launch(void* const* d_in, const int* in_sizes, int n_in,
                              void* d_out, int out_size)
{
    const float* feat   = (const float*)d_in[0];
    const float* affine = (const float*)d_in[1];
    const int*   src    = (const int*)  d_in[2];
    const int*   dst    = (const int*)  d_in[3];
    const float* W      = (const float*)d_in[4];
    const float* bias   = (const float*)d_in[5];
    float*       out    = (float*)d_out;

    const int n_nodes = in_sizes[0] / D_FEAT;
    const int n_edges = in_sizes[1];

    cudaFuncSetAttribute(gemm_kernel,
                         cudaFuncAttributeMaxDynamicSharedMemorySize, SM_TOTAL);

    wprep_kernel<<<16, 256>>>(W);

    int e4 = (n_edges + 3) / 4;
    rowptr_kernel<<<(e4 + 255) / 256, 256>>>(dst, n_nodes, n_edges);

    agg_kernel<<<(n_nodes * 32 + 255) / 256, 256>>>(
        reinterpret_cast<const float4*>(feat), affine, src, n_nodes);

    gemm_kernel<<<(n_nodes + MT - 1) / MT, 256, SM_TOTAL>>>(
        feat, bias, out, n_nodes);
}